// round 2
// baseline (speedup 1.0000x reference)
#include <cuda_runtime.h>

#define BATCH 8
#define NPTS 2048
#define DIM 32
#define KNN 16
#define PINNER 64
#define VINNER 4
#define NTOT (BATCH*NPTS)          /* 16384 */
#define YOFF (NTOT*DIM)            /* 524288 */

// -------- scratch (device globals: no allocation allowed) --------
__device__ float g_xA[NTOT*DIM];
__device__ float g_xB[NTOT*DIM];
__device__ float g_xC[NTOT*DIM];
__device__ int   g_idx[NTOT*KNN];

// -------- weights in constant memory --------
__constant__ float c_Aw[DIM*DIM];
__constant__ float c_Ab[DIM];
__constant__ float c_Bw[DIM*DIM];
__constant__ float c_Bb[DIM];
__constant__ float c_Cw[DIM*DIM];
__constant__ float c_Cb[DIM];
__constant__ float c_pm1w[3*PINNER];     // [3][64]
__constant__ float c_pm1b[PINNER];
__constant__ float c_pm2w[PINNER*DIM];   // [64][32]
__constant__ float c_pm2b[DIM];
__constant__ float c_vm1w[DIM*VINNER];   // [32][4]
__constant__ float c_vm1b[VINNER];
__constant__ float c_vm2w[VINNER*DIM];   // [4][32]
__constant__ float c_vm2b[DIM];

// Exact (non-FMA-contracted) squared distance, matching XLA's
// mul/mul/mul + sequential-add lowering of sum((pi-pj)**2, -1).
__device__ __forceinline__ float sqdist_exact(float dx, float dy, float dz) {
    return __fadd_rn(__fadd_rn(__fmul_rn(dx, dx), __fmul_rn(dy, dy)),
                     __fmul_rn(dz, dz));
}

// ============================================================
// Kernel 1: xA = x@A+a, xB = x@B+b, xC = x@C+c ; p passthrough
// ============================================================
__global__ void __launch_bounds__(128) feat_kernel(const float* __restrict__ x,
                                                   const float* __restrict__ p,
                                                   float* __restrict__ out) {
    int pt = blockIdx.x * 128 + threadIdx.x;
    if (pt >= NTOT) return;

    float xr[DIM];
    const float4* xv = (const float4*)(x + pt * DIM);
#pragma unroll
    for (int q = 0; q < 8; q++) {
        float4 v = xv[q];
        xr[4*q+0] = v.x; xr[4*q+1] = v.y; xr[4*q+2] = v.z; xr[4*q+3] = v.w;
    }

    float acc[DIM];
    // ---- A ----
#pragma unroll
    for (int c = 0; c < DIM; c++) acc[c] = c_Ab[c];
#pragma unroll
    for (int d = 0; d < DIM; d++) {
        float xd = xr[d];
#pragma unroll
        for (int c = 0; c < DIM; c++) acc[c] = fmaf(xd, c_Aw[d*DIM + c], acc[c]);
    }
    {
        float4* o4 = (float4*)(g_xA + pt * DIM);
#pragma unroll
        for (int q = 0; q < 8; q++)
            o4[q] = make_float4(acc[4*q], acc[4*q+1], acc[4*q+2], acc[4*q+3]);
    }
    // ---- B ----
#pragma unroll
    for (int c = 0; c < DIM; c++) acc[c] = c_Bb[c];
#pragma unroll
    for (int d = 0; d < DIM; d++) {
        float xd = xr[d];
#pragma unroll
        for (int c = 0; c < DIM; c++) acc[c] = fmaf(xd, c_Bw[d*DIM + c], acc[c]);
    }
    {
        float4* o4 = (float4*)(g_xB + pt * DIM);
#pragma unroll
        for (int q = 0; q < 8; q++)
            o4[q] = make_float4(acc[4*q], acc[4*q+1], acc[4*q+2], acc[4*q+3]);
    }
    // ---- C ----
#pragma unroll
    for (int c = 0; c < DIM; c++) acc[c] = c_Cb[c];
#pragma unroll
    for (int d = 0; d < DIM; d++) {
        float xd = xr[d];
#pragma unroll
        for (int c = 0; c < DIM; c++) acc[c] = fmaf(xd, c_Cw[d*DIM + c], acc[c]);
    }
    {
        float4* o4 = (float4*)(g_xC + pt * DIM);
#pragma unroll
        for (int q = 0; q < 8; q++)
            o4[q] = make_float4(acc[4*q], acc[4*q+1], acc[4*q+2], acc[4*q+3]);
    }

    // p passthrough -> second part of output
    out[YOFF + pt*3 + 0] = p[pt*3 + 0];
    out[YOFF + pt*3 + 1] = p[pt*3 + 1];
    out[YOFF + pt*3 + 2] = p[pt*3 + 2];
}

// ============================================================
// Kernel 2: 16-NN (top-17 by squared distance, drop first).
// One warp per query; per-lane cached top-3; warp-shuffle argmin
// extraction with (dist, index) lexicographic order to match
// jax.lax.top_k stable tie-breaking.
// ============================================================
__device__ __forceinline__ void ins3(float d, int j,
                                     float& d0, int& i0,
                                     float& d1, int& i1,
                                     float& d2, int& i2) {
    // within a lane, candidates arrive with strictly increasing j,
    // so a strict '<' keeps the smaller index on exact ties.
    if (d < d2) {
        if (d < d1) {
            d2 = d1; i2 = i1;
            if (d < d0) { d1 = d0; i1 = i0; d0 = d; i0 = j; }
            else        { d1 = d;  i1 = j; }
        } else { d2 = d; i2 = j; }
    }
}

__global__ void __launch_bounds__(256) knn_kernel(const float* __restrict__ p) {
    __shared__ float spx[NPTS], spy[NPTS], spz[NPTS];
    __shared__ unsigned sbm[8][64];   // per-warp extracted bitmap

    int tid = threadIdx.x;
    int b = blockIdx.x >> 8;                 // 256 blocks per batch
    int qbase = (blockIdx.x & 255) << 3;     // 8 queries per block
    const float* pb = p + b * NPTS * 3;

    for (int u = tid; u < NPTS*3; u += 256) {
        float v = pb[u];
        int i = u / 3, c = u - 3*i;
        if (c == 0) spx[i] = v; else if (c == 1) spy[i] = v; else spz[i] = v;
    }
    int warp = tid >> 5, lane = tid & 31;
    sbm[warp][lane] = 0u;
    sbm[warp][lane + 32] = 0u;
    __syncthreads();

    int qi = qbase + warp;
    float qx = spx[qi], qy = spy[qi], qz = spz[qi];

    const float INF_F = __int_as_float(0x7f800000);
    float d0 = INF_F, d1 = INF_F, d2 = INF_F;
    int   i0 = 0x7fffffff, i1 = 0x7fffffff, i2 = 0x7fffffff;

#pragma unroll 4
    for (int t = 0; t < 64; t++) {
        int j = lane + (t << 5);
        float d = sqdist_exact(qx - spx[j], qy - spy[j], qz - spz[j]);
        ins3(d, j, d0, i0, d1, i1, d2, i2);
    }

    int* oi_ptr = g_idx + (b * NPTS + qi) * KNN;

    for (int r = 0; r < KNN + 1; r++) {
        float bd = d0; int bi = i0; int bl = lane;
#pragma unroll
        for (int off = 16; off > 0; off >>= 1) {
            float od = __shfl_down_sync(0xffffffffu, bd, off);
            int   oi = __shfl_down_sync(0xffffffffu, bi, off);
            int   ol = __shfl_down_sync(0xffffffffu, bl, off);
            if (od < bd || (od == bd && oi < bi)) { bd = od; bi = oi; bl = ol; }
        }
        bi = __shfl_sync(0xffffffffu, bi, 0);
        bl = __shfl_sync(0xffffffffu, bl, 0);

        if (lane == 0) {
            if (r > 0) oi_ptr[r - 1] = bi;   // round 0 == nearest (self), dropped
            sbm[warp][bi >> 5] |= 1u << (bi & 31);
        }
        __syncwarp();

        if (lane == bl) {
            d0 = d1; i0 = i1; d1 = d2; i1 = i2; d2 = INF_F; i2 = 0x7fffffff;
            if (!(d0 < INF_F)) {
                // cached top-3 exhausted: rescan this lane's 64 candidates
                d0 = d1 = d2 = INF_F; i0 = i1 = i2 = 0x7fffffff;
                for (int t = 0; t < 64; t++) {
                    int j = lane + (t << 5);
                    if ((sbm[warp][j >> 5] >> (j & 31)) & 1u) continue;
                    float d = sqdist_exact(qx - spx[j], qy - spy[j], qz - spz[j]);
                    ins3(d, j, d0, i0, d1, i1, d2, i2);
                }
            }
        }
        __syncwarp();
    }
}

// ============================================================
// Kernel 3: fused gather + position MLP + value MLP + softmax + y.
// 128 threads = 8 points x 16 neighbors. Shared arrays padded to
// stride 33 to avoid 32-way bank conflicts on [pt][k][c] writes.
// ============================================================
__global__ void __launch_bounds__(128) attn_kernel(const float* __restrict__ p,
                                                   float* __restrict__ out) {
    __shared__ float s_xi[8][33];
    __shared__ float s_h2[8][16][33];
    __shared__ float s_val[8][16][33];

    int tid = threadIdx.x;
    int gp0 = blockIdx.x << 3;

    for (int u = tid; u < 8 * DIM; u += 128)
        s_xi[u >> 5][u & 31] = g_xA[(gp0 << 5) + u];
    __syncthreads();

    int pt = tid >> 4, k = tid & 15;
    int gp = gp0 + pt;
    int b = gp >> 11, ii = gp & 2047;
    int j = g_idx[(gp << 4) + k];

    const float* pb = p + b * NPTS * 3;
    float dx = pb[ii*3 + 0] - pb[j*3 + 0];
    float dy = pb[ii*3 + 1] - pb[j*3 + 1];
    float dz = pb[ii*3 + 2] - pb[j*3 + 2];

    // posi_diff MLP: 3 -> 64 (relu) -> 32, hidden in 4 chunks of 16
    float pd[DIM];
#pragma unroll
    for (int c = 0; c < DIM; c++) pd[c] = c_pm2b[c];
#pragma unroll
    for (int ch = 0; ch < 4; ch++) {
        float h1[16];
#pragma unroll
        for (int m = 0; m < 16; m++) {
            int mg = (ch << 4) + m;
            float v = c_pm1b[mg];
            v = fmaf(dx, c_pm1w[mg], v);
            v = fmaf(dy, c_pm1w[64 + mg], v);
            v = fmaf(dz, c_pm1w[128 + mg], v);
            h1[m] = fmaxf(v, 0.0f);
        }
#pragma unroll
        for (int m = 0; m < 16; m++) {
            int mg = (ch << 4) + m;
#pragma unroll
            for (int c = 0; c < DIM; c++)
                pd[c] = fmaf(h1[m], c_pm2w[mg * DIM + c], pd[c]);
        }
    }

    // gather neighbor feature rows
    int row = (b << 11) + j;
    const float4* xb4 = (const float4*)(g_xB + (row << 5));
    const float4* xc4 = (const float4*)(g_xC + (row << 5));

    float hv[4] = { c_vm1b[0], c_vm1b[1], c_vm1b[2], c_vm1b[3] };
#pragma unroll
    for (int q = 0; q < 8; q++) {
        float4 vb = xb4[q];
        float4 vc = xc4[q];
        float hb[4] = { vb.x, vb.y, vb.z, vb.w };
        float hc[4] = { vc.x, vc.y, vc.z, vc.w };
#pragma unroll
        for (int r2 = 0; r2 < 4; r2++) {
            int c = (q << 2) + r2;
            float h = s_xi[pt][c] - hb[r2] + pd[c];
#pragma unroll
            for (int jj = 0; jj < 4; jj++)
                hv[jj] = fmaf(h, c_vm1w[c * 4 + jj], hv[jj]);
            s_val[pt][k][c] = pd[c] + hc[r2];
        }
    }
#pragma unroll
    for (int jj = 0; jj < 4; jj++) hv[jj] = fmaxf(hv[jj], 0.0f);

#pragma unroll
    for (int c = 0; c < DIM; c++) {
        float h2 = c_vm2b[c];
        h2 = fmaf(hv[0], c_vm2w[c],      h2);
        h2 = fmaf(hv[1], c_vm2w[32 + c], h2);
        h2 = fmaf(hv[2], c_vm2w[64 + c], h2);
        h2 = fmaf(hv[3], c_vm2w[96 + c], h2);
        s_h2[pt][k][c] = h2;
    }
    __syncthreads();

    // softmax over k per (pt, c) + weighted sum
    for (int task = tid; task < 256; task += 128) {
        int tp = task >> 5, c = task & 31;
        float m = s_h2[tp][0][c];
#pragma unroll
        for (int kk = 1; kk < 16; kk++) m = fmaxf(m, s_h2[tp][kk][c]);
        float s = 0.0f, acc = 0.0f;
#pragma unroll
        for (int kk = 0; kk < 16; kk++) {
            float e = __expf(s_h2[tp][kk][c] - m);
            s += e;
            acc = fmaf(e, s_val[tp][kk][c], acc);
        }
        out[((gp0 + tp) << 5) + c] = acc / s;
    }
}

// ============================================================
extern "C" void kernel_launch(void* const* d_in, const int* in_sizes, int n_in,
                              void* d_out, int out_size) {
    const float* x = (const float*)d_in[0];
    const float* p = (const float*)d_in[1];

    cudaMemcpyToSymbolAsync(c_Aw,   d_in[2],  DIM*DIM*sizeof(float),     0, cudaMemcpyDeviceToDevice, 0);
    cudaMemcpyToSymbolAsync(c_Ab,   d_in[3],  DIM*sizeof(float),         0, cudaMemcpyDeviceToDevice, 0);
    cudaMemcpyToSymbolAsync(c_Bw,   d_in[4],  DIM*DIM*sizeof(float),     0, cudaMemcpyDeviceToDevice, 0);
    cudaMemcpyToSymbolAsync(c_Bb,   d_in[5],  DIM*sizeof(float),         0, cudaMemcpyDeviceToDevice, 0);
    cudaMemcpyToSymbolAsync(c_Cw,   d_in[6],  DIM*DIM*sizeof(float),     0, cudaMemcpyDeviceToDevice, 0);
    cudaMemcpyToSymbolAsync(c_Cb,   d_in[7],  DIM*sizeof(float),         0, cudaMemcpyDeviceToDevice, 0);
    cudaMemcpyToSymbolAsync(c_pm1w, d_in[8],  3*PINNER*sizeof(float),    0, cudaMemcpyDeviceToDevice, 0);
    cudaMemcpyToSymbolAsync(c_pm1b, d_in[9],  PINNER*sizeof(float),      0, cudaMemcpyDeviceToDevice, 0);
    cudaMemcpyToSymbolAsync(c_pm2w, d_in[10], PINNER*DIM*sizeof(float),  0, cudaMemcpyDeviceToDevice, 0);
    cudaMemcpyToSymbolAsync(c_pm2b, d_in[11], DIM*sizeof(float),         0, cudaMemcpyDeviceToDevice, 0);
    cudaMemcpyToSymbolAsync(c_vm1w, d_in[12], DIM*VINNER*sizeof(float),  0, cudaMemcpyDeviceToDevice, 0);
    cudaMemcpyToSymbolAsync(c_vm1b, d_in[13], VINNER*sizeof(float),      0, cudaMemcpyDeviceToDevice, 0);
    cudaMemcpyToSymbolAsync(c_vm2w, d_in[14], VINNER*DIM*sizeof(float),  0, cudaMemcpyDeviceToDevice, 0);
    cudaMemcpyToSymbolAsync(c_vm2b, d_in[15], DIM*sizeof(float),         0, cudaMemcpyDeviceToDevice, 0);

    feat_kernel<<<NTOT/128, 128>>>(x, p, (float*)d_out);
    knn_kernel<<<NTOT/8, 256>>>(p);
    attn_kernel<<<NTOT/8, 128>>>(p, (float*)d_out);
}

// round 3
// speedup vs baseline: 1.0979x; 1.0979x over previous
#include <cuda_runtime.h>

#define BATCH 8
#define NPTS 2048
#define DIM 32
#define KNN 16
#define PINNER 64
#define VINNER 4
#define NTOT (BATCH*NPTS)          /* 16384 */
#define YOFF (NTOT*DIM)            /* 524288 */

#define KNN_BLOCKS (NTOT/8)        /* 2048: 8 queries/block */
#define FEAT_BLOCKS (NTOT/32)      /* 512: 32 points/block  */

typedef unsigned long long u64;

// -------- scratch (device globals: no allocation allowed) --------
__device__ float g_xA[NTOT*DIM];
__device__ float g_xB[NTOT*DIM];
__device__ float g_xC[NTOT*DIM];
__device__ int   g_idx[NTOT*KNN];

// -------- packed f32x2 helpers (sm_100a PTX) --------
#define PACK2(d, lo, hi) \
    asm("mov.b64 %0, {%1, %2};" : "=l"(d) : "r"(__float_as_uint(lo)), "r"(__float_as_uint(hi)))
#define UNPACK2(lo, hi, s) do { unsigned _ulo, _uhi; \
    asm("mov.b64 {%0, %1}, %2;" : "=r"(_ulo), "=r"(_uhi) : "l"(s)); \
    lo = __uint_as_float(_ulo); hi = __uint_as_float(_uhi); } while(0)
#define FMA2(acc, a, b) \
    asm("fma.rn.f32x2 %0, %1, %2, %0;" : "+l"(acc) : "l"(a), "l"(b))
#define ADD2(d, a, b) \
    asm("add.rn.f32x2 %0, %1, %2;" : "=l"(d) : "l"(a), "l"(b))
#define SUB2(d, a, b) \
    asm("sub.rn.f32x2 %0, %1, %2;" : "=l"(d) : "l"(a), "l"(b))

// Exact (non-FMA-contracted) squared distance, matching XLA's
// mul/mul/mul + sequential-add lowering of sum((pi-pj)**2, -1).
__device__ __forceinline__ float sqdist_exact(float dx, float dy, float dz) {
    return __fadd_rn(__fadd_rn(__fmul_rn(dx, dx), __fmul_rn(dy, dy)),
                     __fmul_rn(dz, dz));
}

#define INFKEY 0xffffffffffffffffULL

__device__ __forceinline__ void ins3u(u64 k, u64& k0, u64& k1, u64& k2) {
    if (k < k2) {
        if (k < k1) {
            k2 = k1;
            if (k < k0) { k1 = k0; k0 = k; }
            else        { k1 = k; }
        } else k2 = k;
    }
}

// ============================================================
// Kernel 1 (fused): blocks [0, KNN_BLOCKS) do 16-NN;
// blocks [KNN_BLOCKS, +FEAT_BLOCKS) do the 3 feature GEMVs + p passthrough.
// ============================================================
__global__ void __launch_bounds__(256) prep_kernel(const float* __restrict__ x,
                                                   const float* __restrict__ p,
                                                   const float* __restrict__ Aw,
                                                   const float* __restrict__ Ab,
                                                   const float* __restrict__ Bw,
                                                   const float* __restrict__ Bb,
                                                   const float* __restrict__ Cw,
                                                   const float* __restrict__ Cb,
                                                   float* __restrict__ out) {
    __shared__ __align__(16) float sm[NPTS*3];   // 24KB: knn p-tile OR feat weights
    int tid = threadIdx.x;
    int warp = tid >> 5, lane = tid & 31;

    if (blockIdx.x < KNN_BLOCKS) {
        // ---------------- KNN branch: warp-per-query, u64 keys ----------------
        int b = blockIdx.x >> 8;                 // 256 blocks per batch
        int qbase = (blockIdx.x & 255) << 3;     // 8 queries per block
        const float* pb = p + b * NPTS * 3;

        for (int u = tid; u < NPTS*3; u += 256) sm[u] = pb[u];
        __syncthreads();

        int qi = qbase + warp;
        float qx = sm[qi*3+0], qy = sm[qi*3+1], qz = sm[qi*3+2];

        u64 k0 = INFKEY, k1 = INFKEY, k2 = INFKEY;
#pragma unroll 4
        for (int t = 0; t < 64; t++) {
            int j = lane + (t << 5);
            float d = sqdist_exact(qx - sm[j*3], qy - sm[j*3+1], qz - sm[j*3+2]);
            u64 key = (((u64)__float_as_uint(d)) << 32) | (unsigned)j;
            ins3u(key, k0, k1, k2);
        }

        int* oi_ptr = g_idx + (b * NPTS + qi) * KNN;
        u64 lp = 0;   // last popped key (pops are strictly increasing per lane)

        for (int r = 0; r < KNN + 1; r++) {
            u64 bk = k0;
#pragma unroll
            for (int off = 16; off > 0; off >>= 1) {
                u64 ok = __shfl_down_sync(0xffffffffu, bk, off);
                bk = (ok < bk) ? ok : bk;
            }
            bk = __shfl_sync(0xffffffffu, bk, 0);

            if (r > 0 && lane == 0)
                oi_ptr[r - 1] = (int)(unsigned)bk;   // round 0 == self, dropped

            if (k0 == bk) {                          // exactly one winner lane
                lp = k0;
                k0 = k1; k1 = k2; k2 = INFKEY;
                if (k0 == INFKEY) {
                    // refill with 3 smallest keys strictly greater than lp
                    for (int t = 0; t < 64; t++) {
                        int j = lane + (t << 5);
                        float d = sqdist_exact(qx - sm[j*3], qy - sm[j*3+1], qz - sm[j*3+2]);
                        u64 key = (((u64)__float_as_uint(d)) << 32) | (unsigned)j;
                        if (key > lp) ins3u(key, k0, k1, k2);
                    }
                }
            }
        }
    } else {
        // ---------------- FEAT branch: warp-per-point (4 pts/warp) ----------------
        float* sAw = sm;            // 1024
        float* sBw = sm + 1024;     // 1024
        float* sCw = sm + 2048;     // 1024
        float* sAb = sm + 3072;     // 32
        float* sBb = sm + 3104;     // 32
        float* sCb = sm + 3136;     // 32

        for (int u = tid; u < 1024; u += 256) {
            sAw[u] = Aw[u]; sBw[u] = Bw[u]; sCw[u] = Cw[u];
        }
        if (tid < 32) { sAb[tid] = Ab[tid]; sBb[tid] = Bb[tid]; sCb[tid] = Cb[tid]; }
        __syncthreads();

        int fb = blockIdx.x - KNN_BLOCKS;
        int pt0 = fb * 32 + warp * 4;
#pragma unroll
        for (int q = 0; q < 4; q++) {
            int pt = pt0 + q;
            float xv = x[pt * DIM + lane];
            float a = sAb[lane], bb = sBb[lane], cc = sCb[lane];
#pragma unroll
            for (int d = 0; d < 32; d++) {
                float xd = __shfl_sync(0xffffffffu, xv, d);
                a  = fmaf(xd, sAw[d*32 + lane], a);
                bb = fmaf(xd, sBw[d*32 + lane], bb);
                cc = fmaf(xd, sCw[d*32 + lane], cc);
            }
            g_xA[pt*DIM + lane] = a;
            g_xB[pt*DIM + lane] = bb;
            g_xC[pt*DIM + lane] = cc;
        }
        // p passthrough -> second part of output (96 floats per feat block)
        if (tid < 96) out[YOFF + fb*96 + tid] = p[fb*96 + tid];
    }
}

// ============================================================
// Kernel 2: fused gather + position MLP + value MLP + softmax + y.
// 128 threads = 8 points x 16 neighbors. f32x2-packed math; weights
// in shared (loaded per block). Pad-34 smem rows: stride 17 (odd) in
// 8B units -> conflict-free 64-bit accesses.
// ============================================================
__global__ void __launch_bounds__(128) attn_kernel(const float* __restrict__ p,
                                                   const float* __restrict__ pm1w,
                                                   const float* __restrict__ pm1b,
                                                   const float* __restrict__ pm2w,
                                                   const float* __restrict__ pm2b,
                                                   const float* __restrict__ vm1w,
                                                   const float* __restrict__ vm1b,
                                                   const float* __restrict__ vm2w,
                                                   const float* __restrict__ vm2b,
                                                   float* __restrict__ out) {
    __shared__ __align__(16) float s_pm1w[192];
    __shared__ __align__(16) float s_pm1b[64];
    __shared__ __align__(16) float s_pm2w[2048];
    __shared__ __align__(16) float s_pm2b[32];
    __shared__ __align__(16) float s_vm1t[128];   // transposed: [jj][c]
    __shared__ __align__(16) float s_vm1b[4];
    __shared__ __align__(16) float s_vm2w[128];   // [jj][c]
    __shared__ __align__(16) float s_vm2b[32];
    __shared__ __align__(16) float s_xi[8][32];
    __shared__ __align__(16) float s_h2[8][16][34];
    __shared__ __align__(16) float s_val[8][16][34];

    int tid = threadIdx.x;
    int gp0 = blockIdx.x << 3;

    // ---- load weights + x_i tile ----
    for (int u = tid; u < 2048; u += 128) s_pm2w[u] = pm2w[u];
    for (int u = tid; u < 192;  u += 128) s_pm1w[u] = pm1w[u];
    if (tid < 64)  s_pm1b[tid] = pm1b[tid];
    if (tid < 32)  { s_pm2b[tid] = pm2b[tid]; s_vm2b[tid] = vm2b[tid]; }
    if (tid < 128) {
        int c = tid >> 2, jj = tid & 3;           // vm1w is [c][jj]
        s_vm1t[jj*32 + c] = vm1w[tid];
        s_vm2w[tid] = vm2w[tid];                  // already [jj][c]
    }
    if (tid < 4) s_vm1b[tid] = vm1b[tid];
    for (int u = tid; u < 256; u += 128)
        s_xi[u >> 5][u & 31] = g_xA[(gp0 << 5) + u];
    __syncthreads();

    int pt = tid >> 4, k = tid & 15;
    int gp = gp0 + pt;
    int b = gp >> 11, ii = gp & 2047;
    int j = g_idx[(gp << 4) + k];

    const float* pb = p + b * NPTS * 3;
    float dx = pb[ii*3 + 0] - pb[j*3 + 0];
    float dy = pb[ii*3 + 1] - pb[j*3 + 1];
    float dz = pb[ii*3 + 2] - pb[j*3 + 2];

    // ---- posi_diff MLP: 3 -> 64 (relu) -> 32, packed accumulators ----
    u64 pd2[16];
#pragma unroll
    for (int i = 0; i < 16; i++)
        pd2[i] = *(const u64*)&s_pm2b[2*i];

#pragma unroll
    for (int ch = 0; ch < 4; ch++) {
        float h1c[16];
#pragma unroll
        for (int m = 0; m < 16; m++) {
            int mg = (ch << 4) + m;
            float v = s_pm1b[mg];
            v = fmaf(dx, s_pm1w[mg],       v);
            v = fmaf(dy, s_pm1w[64 + mg],  v);
            v = fmaf(dz, s_pm1w[128 + mg], v);
            h1c[m] = fmaxf(v, 0.0f);
        }
#pragma unroll
        for (int m = 0; m < 16; m++) {
            int mg = (ch << 4) + m;
            u64 hp; PACK2(hp, h1c[m], h1c[m]);
            const ulonglong2* wr = (const ulonglong2*)&s_pm2w[mg * 32];
#pragma unroll
            for (int i = 0; i < 8; i++) {
                ulonglong2 w = wr[i];                  // LDS.128 = 2 weight pairs
                FMA2(pd2[2*i],     hp, w.x);
                FMA2(pd2[2*i + 1], hp, w.y);
            }
        }
    }

    // ---- gather neighbor rows; h = xi - xB + pd ; vm1 ; val = pd + xC ----
    int row = (b << 11) + j;
    const float4* xb4 = (const float4*)(g_xB + (row << 5));
    const float4* xc4 = (const float4*)(g_xC + (row << 5));

    u64 acc2[4] = {0ull, 0ull, 0ull, 0ull};
#pragma unroll
    for (int q = 0; q < 8; q++) {
        float4 vb = xb4[q];
        float4 vc = xc4[q];
#pragma unroll
        for (int half = 0; half < 2; half++) {
            int pi = 2*q + half;
            int c0 = 4*q + 2*half;
            u64 xbp, xcp;
            if (half == 0) { PACK2(xbp, vb.x, vb.y); PACK2(xcp, vc.x, vc.y); }
            else           { PACK2(xbp, vb.z, vb.w); PACK2(xcp, vc.z, vc.w); }
            u64 xip = *(const u64*)&s_xi[pt][c0];
            u64 t, hpair;
            SUB2(t, xip, xbp);
            ADD2(hpair, t, pd2[pi]);
#pragma unroll
            for (int jj = 0; jj < 4; jj++)
                FMA2(acc2[jj], hpair, *(const u64*)&s_vm1t[jj*32 + c0]);
            u64 valp;
            ADD2(valp, pd2[pi], xcp);
            *(u64*)&s_val[pt][k][c0] = valp;
        }
    }

    float hv[4];
#pragma unroll
    for (int jj = 0; jj < 4; jj++) {
        float lo, hi; UNPACK2(lo, hi, acc2[jj]);
        hv[jj] = fmaxf(lo + hi + s_vm1b[jj], 0.0f);
    }

    // ---- vm2: h2 = vm2b + hv @ vm2w  (packed over c-pairs) ----
    u64 hvp[4];
#pragma unroll
    for (int jj = 0; jj < 4; jj++) PACK2(hvp[jj], hv[jj], hv[jj]);
#pragma unroll
    for (int pi = 0; pi < 16; pi++) {
        int c0 = 2*pi;
        u64 h2p = *(const u64*)&s_vm2b[c0];
#pragma unroll
        for (int jj = 0; jj < 4; jj++)
            FMA2(h2p, hvp[jj], *(const u64*)&s_vm2w[jj*32 + c0]);
        *(u64*)&s_h2[pt][k][c0] = h2p;
    }
    __syncthreads();

    // ---- softmax over k per (pt, c) + weighted sum ----
    for (int task = tid; task < 256; task += 128) {
        int tp = task >> 5, c = task & 31;
        float m = s_h2[tp][0][c];
#pragma unroll
        for (int kk = 1; kk < 16; kk++) m = fmaxf(m, s_h2[tp][kk][c]);
        float s = 0.0f, acc = 0.0f;
#pragma unroll
        for (int kk = 0; kk < 16; kk++) {
            float e = __expf(s_h2[tp][kk][c] - m);
            s += e;
            acc = fmaf(e, s_val[tp][kk][c], acc);
        }
        out[((gp0 + tp) << 5) + c] = acc / s;
    }
}

// ============================================================
extern "C" void kernel_launch(void* const* d_in, const int* in_sizes, int n_in,
                              void* d_out, int out_size) {
    const float* x = (const float*)d_in[0];
    const float* p = (const float*)d_in[1];

    prep_kernel<<<KNN_BLOCKS + FEAT_BLOCKS, 256>>>(
        x, p,
        (const float*)d_in[2], (const float*)d_in[3],
        (const float*)d_in[4], (const float*)d_in[5],
        (const float*)d_in[6], (const float*)d_in[7],
        (float*)d_out);

    attn_kernel<<<NTOT/8, 128>>>(
        p,
        (const float*)d_in[8],  (const float*)d_in[9],
        (const float*)d_in[10], (const float*)d_in[11],
        (const float*)d_in[12], (const float*)d_in[13],
        (const float*)d_in[14], (const float*)d_in[15],
        (float*)d_out);
}

// round 4
// speedup vs baseline: 1.1119x; 1.0127x over previous
#include <cuda_runtime.h>

#define BATCH 8
#define NPTS 2048
#define DIM 32
#define KNN 16
#define NTOT (BATCH*NPTS)          /* 16384 */
#define YOFF (NTOT*DIM)            /* 524288 */

#define KNN_BLOCKS (NTOT/8)        /* 2048: 8 queries/block */
#define FEAT_BLOCKS (NTOT/32)      /* 512: 32 points/block  */

typedef unsigned long long u64;

// -------- scratch (device globals: no allocation allowed) --------
__device__ float g_xA[NTOT*DIM];
__device__ float g_xB[NTOT*DIM];
__device__ float g_xC[NTOT*DIM];
__device__ int   g_idx[NTOT*KNN];

// -------- packed f32x2 helpers (sm_100a PTX) --------
#define PACK2(d, lo, hi) \
    asm("mov.b64 %0, {%1, %2};" : "=l"(d) : "r"(__float_as_uint(lo)), "r"(__float_as_uint(hi)))
#define UNPACK2(lo, hi, s) do { unsigned _ulo, _uhi; \
    asm("mov.b64 {%0, %1}, %2;" : "=r"(_ulo), "=r"(_uhi) : "l"(s)); \
    lo = __uint_as_float(_ulo); hi = __uint_as_float(_uhi); } while(0)
#define FMA2(acc, a, b) \
    asm("fma.rn.f32x2 %0, %1, %2, %0;" : "+l"(acc) : "l"(a), "l"(b))
#define ADD2(d, a, b) \
    asm("add.rn.f32x2 %0, %1, %2;" : "=l"(d) : "l"(a), "l"(b))
#define SUB2(d, a, b) \
    asm("sub.rn.f32x2 %0, %1, %2;" : "=l"(d) : "l"(a), "l"(b))

// Exact (non-FMA-contracted) squared distance, matching XLA's
// mul/mul/mul + sequential-add lowering of sum((pi-pj)**2, -1).
__device__ __forceinline__ float sqdist_exact(float dx, float dy, float dz) {
    return __fadd_rn(__fadd_rn(__fmul_rn(dx, dx), __fmul_rn(dy, dy)),
                     __fmul_rn(dz, dz));
}

#define INFKEY 0xffffffffffffffffULL

__device__ __forceinline__ void ins3u(u64 k, u64& k0, u64& k1, u64& k2) {
    if (k < k2) {
        if (k < k1) {
            k2 = k1;
            if (k < k0) { k1 = k0; k0 = k; }
            else        { k1 = k; }
        } else k2 = k;
    }
}

__device__ __forceinline__ u64 shfl_xor_u64(u64 v, int m) {
    unsigned lo = (unsigned)v, hi = (unsigned)(v >> 32);
    lo = __shfl_xor_sync(0xffffffffu, lo, m);
    hi = __shfl_xor_sync(0xffffffffu, hi, m);
    return (((u64)hi) << 32) | lo;
}

// ============================================================
// Kernel 1 (fused): blocks [0, KNN_BLOCKS) do 16-NN;
// blocks [KNN_BLOCKS, +FEAT_BLOCKS) do the 3 feature GEMVs + p passthrough.
// ============================================================
__global__ void __launch_bounds__(256) prep_kernel(const float* __restrict__ x,
                                                   const float* __restrict__ p,
                                                   const float* __restrict__ Aw,
                                                   const float* __restrict__ Ab,
                                                   const float* __restrict__ Bw,
                                                   const float* __restrict__ Bb,
                                                   const float* __restrict__ Cw,
                                                   const float* __restrict__ Cb,
                                                   float* __restrict__ out) {
    __shared__ __align__(16) float4 sm4[NPTS];   // 32KB
    int tid = threadIdx.x;
    int warp = tid >> 5, lane = tid & 31;

    if (blockIdx.x < KNN_BLOCKS) {
        // ---------------- KNN branch: warp-per-query, u64 keys ----------------
        int b = blockIdx.x >> 8;                 // 256 blocks per batch
        int qbase = (blockIdx.x & 255) << 3;     // 8 queries per block
        const float* pb = p + b * NPTS * 3;

        for (int u = tid; u < NPTS; u += 256)
            sm4[u] = make_float4(pb[3*u], pb[3*u+1], pb[3*u+2], 0.0f);
        __syncthreads();

        int qi = qbase + warp;
        float4 q4 = sm4[qi];

        u64 k0 = INFKEY, k1 = INFKEY, k2 = INFKEY;
#pragma unroll 4
        for (int t = 0; t < 64; t++) {
            int j = lane + (t << 5);
            float4 c4 = sm4[j];
            float d = sqdist_exact(q4.x - c4.x, q4.y - c4.y, q4.z - c4.z);
            u64 key = (((u64)__float_as_uint(d)) << 32) | (unsigned)j;
            ins3u(key, k0, k1, k2);
        }

        int* oi_ptr = g_idx + (b * NPTS + qi) * KNN;
        u64 lp = 0;   // last popped key (pops are strictly increasing)

        for (int r = 0; r < KNN + 1; r++) {
            u64 bk = k0;
#pragma unroll
            for (int off = 16; off > 0; off >>= 1) {
                u64 ok = shfl_xor_u64(bk, off);
                bk = (ok < bk) ? ok : bk;
            }
            if (r > 0 && lane == 0)
                oi_ptr[r - 1] = (int)(unsigned)bk;   // round 0 == self, dropped

            if (k0 == bk) {                          // exactly one winner lane
                lp = k0;
                k0 = k1; k1 = k2; k2 = INFKEY;
                if (k0 == INFKEY) {
                    // refill with 3 smallest keys strictly greater than lp
                    for (int t = 0; t < 64; t++) {
                        int j = lane + (t << 5);
                        float4 c4 = sm4[j];
                        float d = sqdist_exact(q4.x - c4.x, q4.y - c4.y, q4.z - c4.z);
                        u64 key = (((u64)__float_as_uint(d)) << 32) | (unsigned)j;
                        if (key > lp) ins3u(key, k0, k1, k2);
                    }
                }
            }
        }
    } else {
        // ---------------- FEAT branch: warp-per-point (4 pts/warp) ----------------
        float* sm = (float*)sm4;
        float* sAw = sm;            // 1024
        float* sBw = sm + 1024;     // 1024
        float* sCw = sm + 2048;     // 1024
        float* sAb = sm + 3072;     // 32
        float* sBb = sm + 3104;     // 32
        float* sCb = sm + 3136;     // 32

        for (int u = tid; u < 1024; u += 256) {
            sAw[u] = Aw[u]; sBw[u] = Bw[u]; sCw[u] = Cw[u];
        }
        if (tid < 32) { sAb[tid] = Ab[tid]; sBb[tid] = Bb[tid]; sCb[tid] = Cb[tid]; }
        __syncthreads();

        int fb = blockIdx.x - KNN_BLOCKS;
        int pt0 = fb * 32 + warp * 4;
#pragma unroll
        for (int q = 0; q < 4; q++) {
            int pt = pt0 + q;
            float xv = x[pt * DIM + lane];
            float a = sAb[lane], bb = sBb[lane], cc = sCb[lane];
#pragma unroll
            for (int d = 0; d < 32; d++) {
                float xd = __shfl_sync(0xffffffffu, xv, d);
                a  = fmaf(xd, sAw[d*32 + lane], a);
                bb = fmaf(xd, sBw[d*32 + lane], bb);
                cc = fmaf(xd, sCw[d*32 + lane], cc);
            }
            g_xA[pt*DIM + lane] = a;
            g_xB[pt*DIM + lane] = bb;
            g_xC[pt*DIM + lane] = cc;
        }
        // p passthrough -> second part of output (96 floats per feat block)
        if (tid < 96) out[YOFF + fb*96 + tid] = p[fb*96 + tid];
    }
}

// ============================================================
// Kernel 2: fused gather + position MLP + value MLP + softmax + y.
// 64 threads = 8 points x 16 neighbors, TWO pairs per thread:
// pair pp covers pt = (tid>>4) + 4*pp. Weight chunks loaded from SMEM
// once serve both pairs -> pm2w LDS traffic per pair halved.
// ============================================================
__global__ void __launch_bounds__(64) attn_kernel(const float* __restrict__ p,
                                                  const float* __restrict__ pm1w,
                                                  const float* __restrict__ pm1b,
                                                  const float* __restrict__ pm2w,
                                                  const float* __restrict__ pm2b,
                                                  const float* __restrict__ vm1w,
                                                  const float* __restrict__ vm1b,
                                                  const float* __restrict__ vm2w,
                                                  const float* __restrict__ vm2b,
                                                  float* __restrict__ out) {
    __shared__ __align__(16) float s_pm1w[192];
    __shared__ __align__(16) float s_pm1b[64];
    __shared__ __align__(16) float s_pm2w[2048];
    __shared__ __align__(16) float s_pm2b[32];
    __shared__ __align__(16) float s_vm1t[128];   // transposed: [jj][c]
    __shared__ __align__(16) float s_vm1b[4];
    __shared__ __align__(16) float s_vm2w[128];   // [jj][c]
    __shared__ __align__(16) float s_vm2b[32];
    __shared__ __align__(16) float s_xi[8][32];
    __shared__ __align__(16) float s_h2[8][16][34];
    __shared__ __align__(16) float s_val[8][16][34];

    int tid = threadIdx.x;
    int gp0 = blockIdx.x << 3;

    // ---- load weights + x_i tile ----
    for (int u = tid; u < 2048; u += 64) s_pm2w[u] = pm2w[u];
    for (int u = tid; u < 192;  u += 64) s_pm1w[u] = pm1w[u];
    if (tid < 64)  s_pm1b[tid] = pm1b[tid];
    if (tid < 32)  { s_pm2b[tid] = pm2b[tid]; s_vm2b[tid] = vm2b[tid]; }
    for (int u = tid; u < 128; u += 64) {
        int c = u >> 2, jj = u & 3;               // vm1w is [c][jj]
        s_vm1t[jj*32 + c] = vm1w[u];
        s_vm2w[u] = vm2w[u];                      // already [jj][c]
    }
    if (tid < 4) s_vm1b[tid] = vm1b[tid];
    for (int u = tid; u < 256; u += 64)
        s_xi[u >> 5][u & 31] = g_xA[(gp0 << 5) + u];
    __syncthreads();

    int k = tid & 15;
    int ptA = tid >> 4;           // 0..3 ; pair B is ptA + 4

    float dxv[2], dyv[2], dzv[2];
    int rowv[2];
    u64 pd[2][16];

#pragma unroll
    for (int pp = 0; pp < 2; pp++) {
        int pt = ptA + 4*pp;
        int gp = gp0 + pt;
        int b = gp >> 11, ii = gp & 2047;
        int j = g_idx[(gp << 4) + k];
        rowv[pp] = (b << 11) + j;
        const float* pb = p + b * NPTS * 3;
        dxv[pp] = pb[ii*3 + 0] - pb[j*3 + 0];
        dyv[pp] = pb[ii*3 + 1] - pb[j*3 + 1];
        dzv[pp] = pb[ii*3 + 2] - pb[j*3 + 2];
#pragma unroll
        for (int i = 0; i < 16; i++)
            pd[pp][i] = *(const u64*)&s_pm2b[2*i];
    }

    // ---- posi_diff MLP: 3 -> 64 (relu) -> 32, both pairs per weight load ----
#pragma unroll
    for (int ch = 0; ch < 4; ch++) {
        float h1[2][16];
#pragma unroll
        for (int pp = 0; pp < 2; pp++)
#pragma unroll
            for (int m = 0; m < 16; m++) {
                int mg = (ch << 4) + m;
                float v = s_pm1b[mg];
                v = fmaf(dxv[pp], s_pm1w[mg],       v);
                v = fmaf(dyv[pp], s_pm1w[64 + mg],  v);
                v = fmaf(dzv[pp], s_pm1w[128 + mg], v);
                h1[pp][m] = fmaxf(v, 0.0f);
            }
#pragma unroll
        for (int m = 0; m < 16; m++) {
            int mg = (ch << 4) + m;
            u64 hpA; PACK2(hpA, h1[0][m], h1[0][m]);
            u64 hpB; PACK2(hpB, h1[1][m], h1[1][m]);
            const ulonglong2* wr = (const ulonglong2*)&s_pm2w[mg * 32];
#pragma unroll
            for (int i = 0; i < 8; i++) {
                ulonglong2 w = wr[i];              // LDS.128 serves BOTH pairs
                FMA2(pd[0][2*i],     hpA, w.x);
                FMA2(pd[0][2*i + 1], hpA, w.y);
                FMA2(pd[1][2*i],     hpB, w.x);
                FMA2(pd[1][2*i + 1], hpB, w.y);
            }
        }
    }

    // ---- per-pair epilogue: gather, vm1, vm2, stage h2/val ----
#pragma unroll
    for (int pp = 0; pp < 2; pp++) {
        int pt = ptA + 4*pp;
        const float4* xb4 = (const float4*)(g_xB + (rowv[pp] << 5));
        const float4* xc4 = (const float4*)(g_xC + (rowv[pp] << 5));

        u64 acc2[4] = {0ull, 0ull, 0ull, 0ull};
#pragma unroll
        for (int q = 0; q < 8; q++) {
            float4 vb = xb4[q];
            float4 vc = xc4[q];
#pragma unroll
            for (int half = 0; half < 2; half++) {
                int pi = 2*q + half;
                int c0 = 4*q + 2*half;
                u64 xbp, xcp;
                if (half == 0) { PACK2(xbp, vb.x, vb.y); PACK2(xcp, vc.x, vc.y); }
                else           { PACK2(xbp, vb.z, vb.w); PACK2(xcp, vc.z, vc.w); }
                u64 xip = *(const u64*)&s_xi[pt][c0];
                u64 t, hpair;
                SUB2(t, xip, xbp);
                ADD2(hpair, t, pd[pp][pi]);
#pragma unroll
                for (int jj = 0; jj < 4; jj++)
                    FMA2(acc2[jj], hpair, *(const u64*)&s_vm1t[jj*32 + c0]);
                u64 valp;
                ADD2(valp, pd[pp][pi], xcp);
                *(u64*)&s_val[pt][k][c0] = valp;
            }
        }

        float hv[4];
#pragma unroll
        for (int jj = 0; jj < 4; jj++) {
            float lo, hi; UNPACK2(lo, hi, acc2[jj]);
            hv[jj] = fmaxf(lo + hi + s_vm1b[jj], 0.0f);
        }

        u64 hvp[4];
#pragma unroll
        for (int jj = 0; jj < 4; jj++) PACK2(hvp[jj], hv[jj], hv[jj]);
#pragma unroll
        for (int pi = 0; pi < 16; pi++) {
            int c0 = 2*pi;
            u64 h2p = *(const u64*)&s_vm2b[c0];
#pragma unroll
            for (int jj = 0; jj < 4; jj++)
                FMA2(h2p, hvp[jj], *(const u64*)&s_vm2w[jj*32 + c0]);
            *(u64*)&s_h2[pt][k][c0] = h2p;
        }
    }
    __syncthreads();

    // ---- softmax over k per (pt, c) + weighted sum ----
    for (int task = tid; task < 256; task += 64) {
        int tp = task >> 5, c = task & 31;
        float m = s_h2[tp][0][c];
#pragma unroll
        for (int kk = 1; kk < 16; kk++) m = fmaxf(m, s_h2[tp][kk][c]);
        float s = 0.0f, acc = 0.0f;
#pragma unroll
        for (int kk = 0; kk < 16; kk++) {
            float e = __expf(s_h2[tp][kk][c] - m);
            s += e;
            acc = fmaf(e, s_val[tp][kk][c], acc);
        }
        out[((gp0 + tp) << 5) + c] = acc / s;
    }
}

// ============================================================
extern "C" void kernel_launch(void* const* d_in, const int* in_sizes, int n_in,
                              void* d_out, int out_size) {
    const float* x = (const float*)d_in[0];
    const float* p = (const float*)d_in[1];

    prep_kernel<<<KNN_BLOCKS + FEAT_BLOCKS, 256>>>(
        x, p,
        (const float*)d_in[2], (const float*)d_in[3],
        (const float*)d_in[4], (const float*)d_in[5],
        (const float*)d_in[6], (const float*)d_in[7],
        (float*)d_out);

    attn_kernel<<<NTOT/8, 64>>>(
        p,
        (const float*)d_in[8],  (const float*)d_in[9],
        (const float*)d_in[10], (const float*)d_in[11],
        (const float*)d_in[12], (const float*)d_in[13],
        (const float*)d_in[14], (const float*)d_in[15],
        (float*)d_out);
}